// round 3
// baseline (speedup 1.0000x reference)
#include <cuda_runtime.h>
#include <math_constants.h>

// RoI max pooling, warp-cooperative row gather.
//   x:    (1, 256, 64, 64) f32   rois: (1, 512, 4) i32 (rx, ry, rw, rh)
//   out:  (512, 256, 7, 7) f32
// dh = rh/7, dw = rw/7 in [1,4]; clipping provably inactive for these ranges.
//
// One warp handles (n, c, c+64, c+128, c+192). Lanes = contiguous columns of
// the current row segment (7*dw <= 28 floats), so every LDG touches only the
// 1-2 cache lines of that segment — the minimum wavefront count for this
// gather. Column maxes accumulate over the dh rows of bin k in registers
// (4 channels -> 4 independent load chains); dw-group reduction via warp
// shuffles (dw warp-uniform); coalesced stores via a small smem bounce.

#define H_    64
#define W_    64
#define CH_   256
#define N_    512
#define CSTR  (64 * H_ * W_)     // 64 channels apart = 262144 floats
#define OUTC  49                 // 7*7
#define NEG_INF (-CUDART_INF_F)

__global__ void __launch_bounds__(256) roipool_warp(
    const float* __restrict__ x,
    const int*   __restrict__ rois,
    float*       __restrict__ out)
{
    const int warpId = threadIdx.x >> 5;        // 0..7
    const int lane   = threadIdx.x & 31;
    const int n      = blockIdx.x >> 3;         // 0..511
    const int c      = ((blockIdx.x & 7) << 3) + warpId;   // 0..63

    const int4 r  = __ldg(((const int4*)rois) + n);
    const int  dh = r.w / 7;                    // warp-uniform, 1..4
    const int  dw = r.z / 7;                    // warp-uniform, 1..4
    const int  wcols  = 7 * dw;                 // 7..28
    const bool active = lane < wcols;
    const int  j      = lane / dw;              // output column of this lane
    const bool leader = active && (lane - j * dw == 0);

    // base points at (c, ry, rx + lane)
    const float* base = x + c * (H_ * W_) + r.y * W_ + r.x + lane;

    __shared__ float sm[8][4][52];              // [warp][ch][49 padded]
    const unsigned FULL = 0xffffffffu;

    #pragma unroll 1
    for (int k = 0; k < 7; ++k) {
        float m0 = NEG_INF, m1 = NEG_INF, m2 = NEG_INF, m3 = NEG_INF;
        const float* p = base + (dh * k) * W_;

        #pragma unroll 1
        for (int t = 0; t < dh; ++t, p += W_) {
            if (active) {
                m0 = fmaxf(m0, __ldg(p));
                m1 = fmaxf(m1, __ldg(p + CSTR));
                m2 = fmaxf(m2, __ldg(p + 2 * CSTR));
                m3 = fmaxf(m3, __ldg(p + 3 * CSTR));
            }
        }

        // Reduce each dw-wide lane group to its leader (l = j*dw).
        if (dw == 2) {
            m0 = fmaxf(m0, __shfl_down_sync(FULL, m0, 1));
            m1 = fmaxf(m1, __shfl_down_sync(FULL, m1, 1));
            m2 = fmaxf(m2, __shfl_down_sync(FULL, m2, 1));
            m3 = fmaxf(m3, __shfl_down_sync(FULL, m3, 1));
        } else if (dw == 3) {
            // need originals for both shuffles (avoid cross-group contamination)
            float a0 = __shfl_down_sync(FULL, m0, 1), b0 = __shfl_down_sync(FULL, m0, 2);
            float a1 = __shfl_down_sync(FULL, m1, 1), b1 = __shfl_down_sync(FULL, m1, 2);
            float a2 = __shfl_down_sync(FULL, m2, 1), b2 = __shfl_down_sync(FULL, m2, 2);
            float a3 = __shfl_down_sync(FULL, m3, 1), b3 = __shfl_down_sync(FULL, m3, 2);
            m0 = fmaxf(m0, fmaxf(a0, b0));
            m1 = fmaxf(m1, fmaxf(a1, b1));
            m2 = fmaxf(m2, fmaxf(a2, b2));
            m3 = fmaxf(m3, fmaxf(a3, b3));
        } else if (dw == 4) {
            m0 = fmaxf(m0, __shfl_down_sync(FULL, m0, 2));
            m1 = fmaxf(m1, __shfl_down_sync(FULL, m1, 2));
            m2 = fmaxf(m2, __shfl_down_sync(FULL, m2, 2));
            m3 = fmaxf(m3, __shfl_down_sync(FULL, m3, 2));
            m0 = fmaxf(m0, __shfl_down_sync(FULL, m0, 1));
            m1 = fmaxf(m1, __shfl_down_sync(FULL, m1, 1));
            m2 = fmaxf(m2, __shfl_down_sync(FULL, m2, 1));
            m3 = fmaxf(m3, __shfl_down_sync(FULL, m3, 1));
        }
        // dw == 1: lane l == j already holds the answer.

        if (leader) {
            const int o = k * 7 + j;
            sm[warpId][0][o] = m0;
            sm[warpId][1][o] = m1;
            sm[warpId][2][o] = m2;
            sm[warpId][3][o] = m3;
        }
    }

    __syncwarp();

    // Coalesced stores: 49 contiguous floats per (n, channel).
    float* o = out + n * (CH_ * OUTC) + c * OUTC;
    #pragma unroll
    for (int ch = 0; ch < 4; ++ch) {
        float* oc = o + ch * 64 * OUTC;
        oc[lane] = sm[warpId][ch][lane];
        if (lane < OUTC - 32)
            oc[32 + lane] = sm[warpId][ch][32 + lane];
    }
}

extern "C" void kernel_launch(void* const* d_in, const int* in_sizes, int n_in,
                              void* d_out, int out_size)
{
    const float* x    = (const float*)d_in[0];
    const int*   rois = (const int*)  d_in[1];
    float*       out  = (float*)d_out;

    // 4096 blocks * 8 warps = 32768 warps = 512 rois * 64 channel-quads
    roipool_warp<<<4096, 256>>>(x, rois, out);
}

// round 5
// speedup vs baseline: 1.0654x; 1.0654x over previous
#include <cuda_runtime.h>
#include <math_constants.h>

// RoI max pooling, warp row-gather with per-dw lane packing.
//   x: (1,256,64,64) f32   rois: (1,512,4) i32 (rx,ry,rw,rh)   out: (512,256,7,7) f32
// dh = rh/7, dw = rw/7, both warp-uniform in [1,4]; clipping provably inactive.
//
// Warp = (roi n, channel c in 0..63) handling channels {c, c+64, c+128, c+192}.
// Lanes are contiguous columns of the current row segment (wavefront-minimal
// gather); idle lanes are packed with extra channels:
//   dw=1: 28 lanes = 7 cols x 4 channels, no shuffles
//   dw=2: 28 lanes = 14 cols x 2 channels, 1-level shuffle, 2 outer iters
//   dw=3: 21 lanes = cols, 4 channels via immediate-offset LDGs, 2 shuffles
//   dw=4: 28 lanes = cols, 4 channels via immediate-offset LDGs, 2 shuffles

#define HW_   4096               // 64*64 floats per channel
#define CSTR  (64 * HW_)         // 64 channels apart
#define OUTC  49
#define NEG_INF (-CUDART_INF_F)

__global__ void __launch_bounds__(256) roipool_v4(
    const float* __restrict__ x,
    const int*   __restrict__ rois,
    float*       __restrict__ out)
{
    const int warpId = threadIdx.x >> 5;
    const int lane   = threadIdx.x & 31;
    const int n      = blockIdx.x >> 3;
    const int c      = ((blockIdx.x & 7) << 3) + warpId;   // 0..63

    const int4 r  = __ldg(((const int4*)rois) + n);
    const int  dh = r.w / 7;     // warp-uniform 1..4
    const int  dw = r.z / 7;     // warp-uniform 1..4

    const float* xb = x + r.y * 64 + r.x;   // (row ry, col rx), channel added below
    __shared__ float sm[8][4][52];
    const unsigned FULL = 0xffffffffu;

    if (dw == 1) {
        // 28 lanes: col 0..6, ch 0..3. No reduction needed.
        const int col = lane % 7;
        const int ch  = lane / 7;
        if (lane < 28) {
            const float* p0 = xb + (c + (ch << 6)) * HW_ + col;
            #pragma unroll 1
            for (int k = 0; k < 7; ++k) {
                const float* p = p0 + (dh * k) * 64;
                float m = __ldg(p);
                #pragma unroll 1
                for (int t = 1; t < dh; ++t) m = fmaxf(m, __ldg(p + t * 64));
                sm[warpId][ch][k * 7 + col] = m;
            }
        }
    } else if (dw == 2) {
        // 28 lanes: col 0..13, half 0..1 -> 2 channels per LDG, 2 outer iters.
        const int col  = lane % 14;
        const int half = lane / 14;            // 2 for lanes 28..31 (inactive)
        const bool act = lane < 28;
        const int  j   = col >> 1;
        const bool leader = act && ((col & 1) == 0);
        #pragma unroll
        for (int cpair = 0; cpair < 2; ++cpair) {
            const int ch = cpair * 2 + (half & 1);
            const float* p0 = xb + (c + (ch << 6)) * HW_ + col;
            #pragma unroll 1
            for (int k = 0; k < 7; ++k) {
                float m = NEG_INF;
                if (act) {
                    const float* p = p0 + (dh * k) * 64;
                    m = __ldg(p);
                    #pragma unroll 1
                    for (int t = 1; t < dh; ++t) m = fmaxf(m, __ldg(p + t * 64));
                }
                m = fmaxf(m, __shfl_down_sync(FULL, m, 1));
                if (leader) sm[warpId][ch][k * 7 + j] = m;
            }
        }
    } else {
        // dw = 3 or 4: lanes = cols (21 or 28), 4 channels via immediate offsets.
        const int  wcols  = 7 * dw;
        const bool act    = lane < wcols;
        const int  j      = (dw == 3) ? (lane / 3) : (lane >> 2);
        const bool leader = act && (lane == j * dw);
        const float* p0 = xb + c * HW_ + lane;
        #pragma unroll 1
        for (int k = 0; k < 7; ++k) {
            float m0 = NEG_INF, m1 = NEG_INF, m2 = NEG_INF, m3 = NEG_INF;
            if (act) {
                const float* p = p0 + (dh * k) * 64;
                m0 = __ldg(p);           m1 = __ldg(p + CSTR);
                m2 = __ldg(p + 2*CSTR);  m3 = __ldg(p + 3*CSTR);
                #pragma unroll 1
                for (int t = 1; t < dh; ++t) {
                    const float* q = p + t * 64;
                    m0 = fmaxf(m0, __ldg(q));           m1 = fmaxf(m1, __ldg(q + CSTR));
                    m2 = fmaxf(m2, __ldg(q + 2*CSTR));  m3 = fmaxf(m3, __ldg(q + 3*CSTR));
                }
            }
            if (dw == 3) {
                float a0 = __shfl_down_sync(FULL, m0, 1), b0 = __shfl_down_sync(FULL, m0, 2);
                float a1 = __shfl_down_sync(FULL, m1, 1), b1 = __shfl_down_sync(FULL, m1, 2);
                float a2 = __shfl_down_sync(FULL, m2, 1), b2 = __shfl_down_sync(FULL, m2, 2);
                float a3 = __shfl_down_sync(FULL, m3, 1), b3 = __shfl_down_sync(FULL, m3, 2);
                m0 = fmaxf(m0, fmaxf(a0, b0));  m1 = fmaxf(m1, fmaxf(a1, b1));
                m2 = fmaxf(m2, fmaxf(a2, b2));  m3 = fmaxf(m3, fmaxf(a3, b3));
            } else {
                m0 = fmaxf(m0, __shfl_down_sync(FULL, m0, 2));
                m1 = fmaxf(m1, __shfl_down_sync(FULL, m1, 2));
                m2 = fmaxf(m2, __shfl_down_sync(FULL, m2, 2));
                m3 = fmaxf(m3, __shfl_down_sync(FULL, m3, 2));
                m0 = fmaxf(m0, __shfl_down_sync(FULL, m0, 1));
                m1 = fmaxf(m1, __shfl_down_sync(FULL, m1, 1));
                m2 = fmaxf(m2, __shfl_down_sync(FULL, m2, 1));
                m3 = fmaxf(m3, __shfl_down_sync(FULL, m3, 1));
            }
            if (leader) {
                const int o = k * 7 + j;
                sm[warpId][0][o] = m0;  sm[warpId][1][o] = m1;
                sm[warpId][2][o] = m2;  sm[warpId][3][o] = m3;
            }
        }
    }

    __syncwarp();

    // Coalesced stores: 49 contiguous floats per (n, channel).
    float* o = out + n * (256 * OUTC) + c * OUTC;
    #pragma unroll
    for (int ch = 0; ch < 4; ++ch) {
        float* oc = o + ch * 64 * OUTC;
        oc[lane] = sm[warpId][ch][lane];
        if (lane < OUTC - 32)
            oc[32 + lane] = sm[warpId][ch][32 + lane];
    }
}

extern "C" void kernel_launch(void* const* d_in, const int* in_sizes, int n_in,
                              void* d_out, int out_size)
{
    const float* x    = (const float*)d_in[0];
    const int*   rois = (const int*)  d_in[1];
    float*       out  = (float*)d_out;

    roipool_v4<<<4096, 256>>>(x, rois, out);   // 512 rois x 64 channel-quads
}